// round 15
// baseline (speedup 1.0000x reference)
#include <cuda_runtime.h>

#define BB 4
#define NN 128
#define IND 256
#define OD 128
#define NEGV (-1.0e9f)
#define EPSV (1e-5f)

// ---------------- scratch (device globals; no allocation) ----------------
__device__ __align__(16) float g_tri1[BB*NN*8];
__device__ __align__(16) float g_tri2[BB*NN*8];
__device__ __align__(16) float g_tri3[BB*NN*8];
__device__ __align__(16) float g_trig[BB*8];
__device__ __align__(16) float g_msgg[BB*OD];
__device__ __align__(16) float g_msg1[BB*NN*OD];
__device__ __align__(16) float g_msg2[BB*NN*OD];
__device__ __align__(16) float g_zU1[BB*NN*OD];
__device__ __align__(16) float g_e1t[BB*NN*NN*8];   // [b][j][i][c]
__device__ __align__(16) float g_e2t[BB*NN*NN*8];   // [b][k][i][c]
__device__ __align__(16) float g_e3n[BB*NN*NN*8];   // [b][j][k][c]
__device__ __align__(16) float g_pmax[BB*2*NN*OD];  // [b][ihalf][j][c]
__device__ unsigned char g_mask[BB*NN];
__device__ unsigned char g_adj[BB*NN*NN];

// order-preserving float<->uint for atomicMax
__device__ __forceinline__ unsigned fkey(float f) {
    unsigned b = __float_as_uint(f);
    return (b & 0x80000000u) ? ~b : (b | 0x80000000u);
}
__device__ __forceinline__ float fdec(unsigned k) {
    return __uint_as_float((k & 0x80000000u) ? (k & 0x7fffffffu) : ~k);
}

// ---------------- bool-dtype detection + canonicalization (parallel) ----------------
__global__ void __launch_bounds__(256) k_convbool(const void* maskp, const void* adjp) {
    __shared__ unsigned sf[8], sg[8];
    int t = threadIdx.x, bi = blockIdx.x, w = t >> 5;
    unsigned f = 0, g = 0;
    const unsigned* aw = (const unsigned*)adjp;
    for (int i = t; i < 16384; i += 256) {
        unsigned v = aw[i];
        f |= (v == 0x3F800000u);
        g |= (v > 1u && v != 0x3F800000u);
    }
    f = __any_sync(0xffffffffu, f);
    g = __any_sync(0xffffffffu, g);
    if ((t & 31) == 0) { sf[w] = f; sg[w] = g; }
    __syncthreads();
    unsigned F = sf[0]|sf[1]|sf[2]|sf[3]|sf[4]|sf[5]|sf[6]|sf[7];
    unsigned G = sg[0]|sg[1]|sg[2]|sg[3]|sg[4]|sg[5]|sg[6]|sg[7];
    int cls = F ? 2 : (G ? 0 : 1);  // 0=u8, 1=i32, 2=f32
    int base = bi*1024;
    if (cls == 0) {
        const unsigned char* a = (const unsigned char*)adjp;
        const unsigned char* m = (const unsigned char*)maskp;
        for (int i = t; i < 1024; i += 256) g_adj[base+i] = a[base+i] ? 1 : 0;
        if (t < 8) g_mask[bi*8+t] = m[bi*8+t] ? 1 : 0;
    } else if (cls == 1) {
        const int* a = (const int*)adjp;
        const int* m = (const int*)maskp;
        for (int i = t; i < 1024; i += 256) g_adj[base+i] = a[base+i] ? 1 : 0;
        if (t < 8) g_mask[bi*8+t] = m[bi*8+t] ? 1 : 0;
    } else {
        const float* a = (const float*)adjp;
        const float* m = (const float*)maskp;
        for (int i = t; i < 1024; i += 256) g_adj[base+i] = (a[base+i] != 0.0f) ? 1 : 0;
        if (t < 8) g_mask[bi*8+t] = (m[bi*8+t] != 0.0f) ? 1 : 0;
    }
}

// ---------------- graph projections ----------------
__global__ void __launch_bounds__(128) k_graph(const float* __restrict__ gf,
                                               const float* __restrict__ Wg,
                                               const float* __restrict__ Wmg) {
    int b = blockIdx.x, c = threadIdx.x;
    __shared__ float gs[IND/2];
    gs[c] = gf[b*(IND/2) + c];
    __syncthreads();
    float acc = 0.f;
    #pragma unroll 4
    for (int k = 0; k < IND/2; k++) acc += gs[k]*Wmg[k*OD + c];
    g_msgg[b*OD + c] = acc;
    if (c < 8) {
        float a = 0.f;
        for (int k = 0; k < IND/2; k++) a += gs[k]*Wg[k*8 + c];
        g_trig[b*8 + c] = a;
    }
}

// ---------------- node projections: smem-staged GEMM, 512 threads ----------------
// zs:1024, Wts:6144, Wc:12288, ptri:192
#define NODE_SMEM_FLOATS 19648
__global__ void __launch_bounds__(512,2) k_node(const float* __restrict__ z,
                                                const float* __restrict__ Wm1,
                                                const float* __restrict__ Wm2,
                                                const float* __restrict__ WU1,
                                                const float* __restrict__ Wt1,
                                                const float* __restrict__ Wt2,
                                                const float* __restrict__ Wt3) {
    extern __shared__ float smn[];
    float* zs   = smn;          // 4*256
    float* Wts  = smn + 1024;   // 256*24
    float* Wc   = smn + 7168;   // 3*32*128
    float* ptri = smn + 19456;  // 192
    int r0 = blockIdx.x*4, t = threadIdx.x;
    int c = t & 127, h = t >> 7;  // h = row within block (0..3)

    {
        float4* zs4 = (float4*)zs;
        const float4* zsrc = (const float4*)(z + (long)r0*IND);
        for (int i = t; i < 256; i += 512) zs4[i] = zsrc[i];
    }
    for (int i = t; i < 2048; i += 512) {
        int k = i >> 3, cc = i & 7;
        Wts[k*24 + cc]      = Wt1[i];
        Wts[k*24 + 8 + cc]  = Wt2[i];
        Wts[k*24 + 16 + cc] = Wt3[i];
    }

    float a1 = 0.f, a2 = 0.f, a3 = 0.f;
    for (int kc = 0; kc < 8; kc++) {
        int k0 = kc*32;
        __syncthreads();
        {
            const float4* s1 = (const float4*)(Wm1 + k0*OD);
            const float4* s2 = (const float4*)(Wm2 + k0*OD);
            const float4* s3 = (const float4*)(WU1 + k0*OD);
            float4* d = (float4*)Wc;
            for (int i = t; i < 1024; i += 512) {
                d[i] = s1[i]; d[1024 + i] = s2[i]; d[2048 + i] = s3[i];
            }
        }
        __syncthreads();
        const float* W1s = Wc, *W2s = Wc + 4096, *W3s = Wc + 8192;
        const float* zp = zs + h*IND + k0;
        #pragma unroll 8
        for (int k = 0; k < 32; k++) {
            float w1 = W1s[k*128 + c], w2 = W2s[k*128 + c], w3 = W3s[k*128 + c];
            float zv = zp[k];
            a1 += zv*w1; a2 += zv*w2; a3 += zv*w3;
        }
    }
    {
        int bn = r0 + h;
        float mk = g_mask[bn] ? 1.0f : 0.0f;
        g_msg1[bn*OD + c] = a1*mk;
        g_msg2[bn*OD + c] = a2*mk;
        g_zU1[bn*OD + c]  = a3;
    }
    // tri projections: 192 threads, split-k halves
    if (t < 192) {
        int rr = t/48, rem = t%48, q = rem >> 1, kh = rem & 1;
        float s = 0.f;
        const float* zr = zs + rr*IND + kh*128;
        const float* wq = Wts + (kh*128)*24 + q;
        #pragma unroll 8
        for (int k = 0; k < 128; k++) s += zr[k]*wq[k*24];
        ptri[t] = s;
    }
    __syncthreads();
    if (t < 96) {
        int rr = t/24, q = t%24;
        float s = ptri[rr*48 + q*2] + ptri[rr*48 + q*2 + 1];
        int bn = r0 + rr;
        s *= (g_mask[bn] ? 1.0f : 0.0f);
        int cc = q & 7;
        if (q < 8)       g_tri1[bn*8 + cc] = s;
        else if (q < 16) g_tri2[bn*8 + cc] = s;
        else             g_tri3[bn*8 + cc] = s;
    }
}

// ---------------- edge projections e @ We1/We2/We3 (R6 version, measured 44us) ----------------
__global__ void __launch_bounds__(256) k_eproj(const float* __restrict__ e,
                                               const float* __restrict__ We1,
                                               const float* __restrict__ We2,
                                               const float* __restrict__ We3) {
    __shared__ float Ws[128*32];   // [k][32]: q*8 + (0..5) used
    __shared__ float es[64*132];   // [r][132]: 33 float4 per row (pad)
    int t = threadIdx.x;
    for (int idx = t; idx < 128*24; idx += 256) {
        int k = idx/24, r = idx%24;
        float v;
        if (r < 8)       v = We1[k*8 + r];
        else if (r < 16) v = We2[k*8 + (r-8)];
        else             v = We3[k*8 + (r-16)];
        Ws[k*32 + (r/6)*8 + (r%6)] = v;
    }
    long row0 = (long)blockIdx.x*64;
    const float4* esrc = (const float4*)(e + row0*128);
    float4* es4 = (float4*)es;
    for (int idx = t; idx < 2048; idx += 256) {
        int r = idx >> 5, kq = idx & 31;
        es4[r*33 + kq] = esrc[idx];
    }
    __syncthreads();
    int r = t >> 2, q = t & 3;
    float acc[6] = {0,0,0,0,0,0};
    const float4* erow4 = es4 + r*33;
    const float* wb = Ws + q*8;
    #pragma unroll 2
    for (int k4 = 0; k4 < 32; k4++) {
        float4 ev = erow4[k4];
        #pragma unroll
        for (int kk = 0; kk < 4; kk++) {
            int k = k4*4 + kk;
            float4 w0 = *(const float4*)(wb + k*32);
            float2 w1 = *(const float2*)(wb + k*32 + 4);
            float evk = (&ev.x)[kk];
            acc[0] += evk*w0.x; acc[1] += evk*w0.y; acc[2] += evk*w0.z;
            acc[3] += evk*w0.w; acc[4] += evk*w1.x; acc[5] += evk*w1.y;
        }
    }
    int row = (int)row0 + r;
    int b = row >> 14, r1 = (row >> 7) & 127, r2 = row & 127; // r1=i, r2=j(or k)
    int tidx = ((b*NN + r2)*NN + r1)*8;
    if (q == 0) {
        *(float4*)&g_e1t[tidx]   = make_float4(acc[0], acc[1], acc[2], acc[3]);
        *(float2*)&g_e1t[tidx+4] = make_float2(acc[4], acc[5]);
    } else if (q == 1) {
        *(float2*)&g_e1t[tidx+6] = make_float2(acc[0], acc[1]);
        *(float4*)&g_e2t[tidx]   = make_float4(acc[2], acc[3], acc[4], acc[5]);
    } else if (q == 2) {
        *(float4*)&g_e2t[tidx+4] = make_float4(acc[0], acc[1], acc[2], acc[3]);
        *(float2*)&g_e3n[row*8]  = make_float2(acc[4], acc[5]);
    } else {
        *(float2*)&g_e3n[row*8+2] = make_float2(acc[0], acc[1]);
        *(float4*)&g_e3n[row*8+4] = make_float4(acc[2], acc[3], acc[4], acc[5]);
    }
}

// ---------------- triplet max-plus core + @WU3 + relu (512thr, 2 blocks/SM) ----------------
#define TRI_SMEM_FLOATS 19352
__global__ void __launch_bounds__(512,2) k_trimax(const float* __restrict__ WU3,
                                                  float* __restrict__ out_tri) {
    extern __shared__ float sm[];
    float* A_s  = sm;            // 1024 (reused as partial buffer after S1+=A)
    float* S1   = sm + 1024;     // 8*1032 (tri1 + E1 fused)
    float* E2s  = sm + 9280;     // 8*1032
    float* pen  = sm + 17536;    // 128
    float* t2s  = sm + 17664;    // 64
    float* t3s  = sm + 17728;    // 64
    float* tgs  = sm + 17792;    // 8
    float* mjf  = sm + 17800;    // 8
    float* mkf  = sm + 17808;    // 8
    float* WU3s = sm + 17816;    // 1024
    float* Ps   = sm + 18840;    // 512
    float* Pp   = A_s;           // 256*4 partials (alias)

    int t = threadIdx.x;
    int jt = blockIdx.x, kt = blockIdx.y, b = blockIdx.z;
    int j0 = jt*8, k0 = kt*8;

    for (int idx = t; idx < 1024; idx += 512) {
        A_s[idx]  = g_tri1[b*1024 + idx];
        WU3s[idx] = WU3[idx];
    }
    {
        float4* S14 = (float4*)S1;
        float4* E24 = (float4*)E2s;
        for (int idx = t; idx < 2048; idx += 512) {
            int s = idx >> 8, r4 = idx & 255;
            S14[s*258 + r4] = ((const float4*)g_e1t)[((b*NN + j0 + s) << 8) + r4];
            E24[s*258 + r4] = ((const float4*)g_e2t)[((b*NN + k0 + s) << 8) + r4];
        }
    }
    if (t < 128) pen[t] = g_mask[b*NN + t] ? 0.0f : -2.0e9f;
    if (t >= 128 && t < 192) t2s[t-128] = g_tri2[b*1024 + j0*8 + (t-128)];
    if (t >= 192 && t < 256) t3s[t-192] = g_tri3[b*1024 + k0*8 + (t-192)];
    if (t >= 256 && t < 264) tgs[t-256] = g_trig[b*8 + (t-256)];
    if (t >= 264 && t < 272) mjf[t-264] = g_mask[b*NN + j0 + (t-264)] ? 1.0f : 0.0f;
    if (t >= 272 && t < 280) mkf[t-272] = g_mask[b*NN + k0 + (t-272)] ? 1.0f : 0.0f;
    __syncthreads();
    {   // S1 += A (broadcast over jj)
        float4* S14 = (float4*)S1;
        const float4* A4 = (const float4*)A_s;
        for (int idx = t; idx < 2048; idx += 512) {
            int s = idx >> 8, r4 = idx & 255;
            float4 v = S14[s*258 + r4], a = A4[r4];
            v.x += a.x; v.y += a.y; v.z += a.z; v.w += a.w;
            S14[s*258 + r4] = v;
        }
    }
    __syncthreads();

    int r = t & 255;
    int ih = t >> 8;             // i-half
    int jj = r >> 5;             // warp-uniform
    int kk = (r >> 2) & 7;
    int cp = (r & 3)*2;
    const float* s1p = S1 + jj*1032 + cp + ih*512;   // +64 i
    const float* e2p = E2s + kk*1032 + cp + ih*512;
    const float* penh = pen + ih*64;
    bool jv = (mjf[jj] != 0.0f);

    float a0a = NEGV, a0b = NEGV, a1a = NEGV, a1b = NEGV;
    float v0a = NEGV, v0b = NEGV, v1a = NEGV, v1b = NEGV;
    if (jv) {
        #pragma unroll 4
        for (int i = 0; i < 64; i += 2) {
            float2 sA = *(const float2*)(s1p + i*8);
            float2 eA = *(const float2*)(e2p + i*8);
            float2 sB = *(const float2*)(s1p + i*8 + 8);
            float2 eB = *(const float2*)(e2p + i*8 + 8);
            a0a = fmaxf(a0a, sA.x + eA.x); a1a = fmaxf(a1a, sA.y + eA.y);
            a0b = fmaxf(a0b, sB.x + eB.x); a1b = fmaxf(a1b, sB.y + eB.y);
        }
    } else {
        #pragma unroll 4
        for (int i = 0; i < 64; i += 2) {
            float2 sA = *(const float2*)(s1p + i*8);
            float2 eA = *(const float2*)(e2p + i*8);
            float2 sB = *(const float2*)(s1p + i*8 + 8);
            float2 eB = *(const float2*)(e2p + i*8 + 8);
            float pA = penh[i], pB = penh[i+1];
            float x0 = sA.x + eA.x, x1 = sA.y + eA.y;
            float y0 = sB.x + eB.x, y1 = sB.y + eB.y;
            a0a = fmaxf(a0a, x0); a1a = fmaxf(a1a, x1);
            a0b = fmaxf(a0b, y0); a1b = fmaxf(a1b, y1);
            v0a = fmaxf(v0a, x0 + pA); v1a = fmaxf(v1a, x1 + pA);
            v0b = fmaxf(v0b, y0 + pB); v1b = fmaxf(v1b, y1 + pB);
        }
    }
    float mA0 = fmaxf(a0a, a0b), mA1 = fmaxf(a1a, a1b);
    float mV0 = fmaxf(v0a, v0b), mV1 = fmaxf(v1a, v1b);

    __syncthreads();   // A_s reads all done; safe to alias as Pp
    if (ih == 1) {
        float4* pp = (float4*)(Pp + r*4);
        *pp = make_float4(mA0, mA1, mV0, mV1);
    }
    __syncthreads();
    if (ih == 0) {
        float4 o = *(const float4*)(Pp + r*4);
        mA0 = fmaxf(mA0, o.x); mA1 = fmaxf(mA1, o.y);
        mV0 = fmaxf(mV0, o.z); mV1 = fmaxf(mV1, o.w);
        bool cond = jv || (mkf[kk] != 0.0f);
        int jg = j0 + jj, kg = k0 + kk;
        float2 e3v = *(const float2*)&g_e3n[((b*NN + jg)*NN + kg)*8 + cp];
        float base0 = t2s[jj*8 + cp]     + t3s[kk*8 + cp]     + tgs[cp]     + e3v.x;
        float base1 = t2s[jj*8 + cp + 1] + t3s[kk*8 + cp + 1] + tgs[cp + 1] + e3v.y;
        float p0 = cond ? (mA0 + base0) : fmaxf(mV0 + base0, NEGV);
        float p1 = cond ? (mA1 + base1) : fmaxf(mV1 + base1, NEGV);
        *(float2*)&Ps[(jj*8 + kk)*8 + cp] = make_float2(p0, p1);
    }
    __syncthreads();

    #pragma unroll
    for (int oi = 0; oi < 16; oi++) {
        int idx = t + 512*oi;
        int jk = idx >> 7, o = idx & 127;
        const float* pr = Ps + jk*8;
        float acc = 0.f;
        #pragma unroll
        for (int c = 0; c < 8; c++) acc += pr[c]*WU3s[c*128 + o];
        acc = fmaxf(acc, 0.0f);
        int jjx = jk >> 3, kkx = jk & 7;
        out_tri[(((long)b*NN + j0 + jjx)*NN + (k0 + kkx))*OD + o] = acc;
    }
}

// ---------------- fused pairwise MLP, 512 threads (16 warps, group of 3) ----------------
__device__ __forceinline__ void ln_relu4(float* x, float4 s, float4 o) {
    float sum = x[0] + x[1] + x[2] + x[3];
    #pragma unroll
    for (int off = 16; off > 0; off >>= 1) sum += __shfl_xor_sync(0xffffffffu, sum, off);
    float mean = sum * 0.0078125f;
    float d0 = x[0]-mean, d1 = x[1]-mean, d2 = x[2]-mean, d3 = x[3]-mean;
    float q = d0*d0 + d1*d1 + d2*d2 + d3*d3;
    #pragma unroll
    for (int off = 16; off > 0; off >>= 1) q += __shfl_xor_sync(0xffffffffu, q, off);
    float rs = rsqrtf(q*0.0078125f + EPSV);
    x[0] = fmaxf(fmaf(s.x*rs, d0, o.x), 0.f);
    x[1] = fmaxf(fmaf(s.y*rs, d1, o.y), 0.f);
    x[2] = fmaxf(fmaf(s.z*rs, d2, o.z), 0.f);
    x[3] = fmaxf(fmaf(s.w*rs, d3, o.w), 0.f);
}

__device__ __forceinline__ void gemv3(const float* eb, const float4* W4, int l,
                                      float a[3][4]) {
    #pragma unroll 2
    for (int k4 = 0; k4 < 32; k4++) {
        float4 v[3];
        #pragma unroll
        for (int q = 0; q < 3; q++) v[q] = ((const float4*)(eb + q*128))[k4];
        #pragma unroll
        for (int kk = 0; kk < 4; kk++) {
            float4 wv = W4[(k4*4 + kk)*32 + l];
            #pragma unroll
            for (int q = 0; q < 3; q++) {
                float f = (&v[q].x)[kk];
                a[q][0] += f*wv.x; a[q][1] += f*wv.y;
                a[q][2] += f*wv.z; a[q][3] += f*wv.w;
            }
        }
    }
}

#define PAIR_SMEM_FLOATS 56864
__global__ void __launch_bounds__(512,1) k_pair(
    const float* __restrict__ e,
    const float* __restrict__ Wme, const float* __restrict__ Wmlp1, const float* __restrict__ Wmlp2,
    const float* __restrict__ ln1s, const float* __restrict__ ln1o,
    const float* __restrict__ ln2s, const float* __restrict__ ln2o) {
    extern __shared__ float sm[];
    float* Wme_s = sm;
    float* W1_s  = sm + 16384;
    float* W2_s  = sm + 32768;
    float* ebuf  = sm + 49152;               // 16 warps * 3 rows * 128 = 6144
    int*   lists = (int*)(sm + 55296);       // 8 cols * 64
    unsigned* smax = (unsigned*)(sm + 55808); // 8 cols * 128
    int*   offs  = (int*)(sm + 56832);       // 17

    int t = threadIdx.x, w = t >> 5, l = t & 31;
    int jt = blockIdx.x, half = blockIdx.y, b = blockIdx.z;

    {
        const float4* a  = (const float4*)Wme;
        const float4* c1 = (const float4*)Wmlp1;
        const float4* c2 = (const float4*)Wmlp2;
        float4* d0 = (float4*)Wme_s; float4* d1 = (float4*)W1_s; float4* d2 = (float4*)W2_s;
        for (int idx = t; idx < 4096; idx += 512) { d0[idx] = a[idx]; d1[idx] = c1[idx]; d2[idx] = c2[idx]; }
    }
    unsigned negkey = fkey(NEGV);
    for (int idx = t; idx < 1024; idx += 512) smax[idx] = negkey;

    if (w < 8) {   // warps 0-7 build the 8 column lists
        int jw = jt*8 + w;
        int* list = lists + w*64;
        int cnt = 0;
        for (int base = 0; base < 64; base += 32) {
            int i = half*64 + base + l;
            int f = g_adj[(b*NN + i)*NN + jw] ? 1 : 0;
            unsigned bal = __ballot_sync(0xffffffffu, f);
            int pos = cnt + __popc(bal & ((1u << l) - 1u));
            if (f) list[pos] = i;
            cnt += __popc(bal);
        }
        if (l == 0) offs[9 + w] = cnt;
    }
    __syncthreads();
    if (t == 0) {
        int s = 0;
        #pragma unroll
        for (int q = 0; q < 8; q++) { offs[q] = s; s += offs[9 + q]; }
        offs[8] = s;
    }
    __syncthreads();
    int E = offs[8];

    int c0 = 4*l;
    float4 mgg = *(const float4*)&g_msgg[b*OD + c0];
    float4 p1s = *(const float4*)&ln1s[c0];
    float4 p1o = *(const float4*)&ln1o[c0];
    float4 p2s = *(const float4*)&ln2s[c0];
    float4 p2o = *(const float4*)&ln2o[c0];

    const float4* Wme4 = (const float4*)Wme_s;
    const float4* W14  = (const float4*)W1_s;
    const float4* W24  = (const float4*)W2_s;
    float* eb = ebuf + w*384;

    for (int g0 = w*3; g0 < E; g0 += 48) {
        int nv = E - g0; if (nv > 3) nv = 3;
        int id[3], jl[3];
        #pragma unroll
        for (int q = 0; q < 3; q++) {
            int fi = g0 + (q < nv ? q : nv-1);
            int c = 0;
            #pragma unroll
            for (int x = 1; x < 8; x++) if (fi >= offs[x]) c = x;
            jl[q] = c;
            id[q] = lists[c*64 + fi - offs[c]];
        }
        float a[3][4];
        #pragma unroll
        for (int q = 0; q < 3; q++) {
            int jq = jt*8 + jl[q];
            float4 m1 = *(const float4*)&g_msg1[(b*NN + jq)*OD + c0];
            float4 m2 = *(const float4*)&g_msg2[(b*NN + id[q])*OD + c0];
            a[q][0] = m1.x + m2.x + mgg.x; a[q][1] = m1.y + m2.y + mgg.y;
            a[q][2] = m1.z + m2.z + mgg.z; a[q][3] = m1.w + m2.w + mgg.w;
        }
        __syncwarp();
        #pragma unroll
        for (int q = 0; q < 3; q++) {
            int jq = jt*8 + jl[q];
            ((float4*)(eb + q*128))[l] = *(const float4*)&e[(((long)b*NN + id[q])*NN + jq)*128 + c0];
        }
        __syncwarp();

        gemv3(eb, Wme4, l, a);
        #pragma unroll
        for (int q = 0; q < 3; q++) ln_relu4(a[q], p1s, p1o);
        __syncwarp();
        #pragma unroll
        for (int q = 0; q < 3; q++)
            ((float4*)(eb + q*128))[l] = make_float4(a[q][0], a[q][1], a[q][2], a[q][3]);
        __syncwarp();

        float a2[3][4];
        #pragma unroll
        for (int q = 0; q < 3; q++) { a2[q][0]=0; a2[q][1]=0; a2[q][2]=0; a2[q][3]=0; }
        gemv3(eb, W14, l, a2);
        #pragma unroll
        for (int q = 0; q < 3; q++) ln_relu4(a2[q], p2s, p2o);
        __syncwarp();
        #pragma unroll
        for (int q = 0; q < 3; q++)
            ((float4*)(eb + q*128))[l] = make_float4(a2[q][0], a2[q][1], a2[q][2], a2[q][3]);
        __syncwarp();

        float a3[3][4];
        #pragma unroll
        for (int q = 0; q < 3; q++) { a3[q][0]=0; a3[q][1]=0; a3[q][2]=0; a3[q][3]=0; }
        gemv3(eb, W24, l, a3);
        #pragma unroll
        for (int q = 0; q < 3; q++) {
            if (q < nv) {
                unsigned* sj = smax + jl[q]*128 + c0;
                atomicMax(&sj[0], fkey(a3[q][0]));
                atomicMax(&sj[1], fkey(a3[q][1]));
                atomicMax(&sj[2], fkey(a3[q][2]));
                atomicMax(&sj[3], fkey(a3[q][3]));
            }
        }
    }
    __syncthreads();
    for (int idx = t; idx < 1024; idx += 512) {
        int jl2 = idx >> 7, c = idx & 127;
        g_pmax[((b*2 + half)*NN + jt*8 + jl2)*OD + c] = fdec(smax[idx]);
    }
}

// ---------------- final: msgs out + ret = LN(zU1 + msgs@WU2) ----------------
__global__ void __launch_bounds__(128) k_final(const float* __restrict__ WU2,
                                               const float* __restrict__ lnfs,
                                               const float* __restrict__ lnfo,
                                               float* __restrict__ out_ret,
                                               float* __restrict__ out_msgs) {
    int bn = blockIdx.x;
    int b = bn >> 7;
    int c = threadIdx.x, l = c & 31, w = c >> 5;
    int n = bn & 127;
    __shared__ float ms[128];
    __shared__ float red[4];
    float m = fmaxf(g_pmax[((b*2 + 0)*NN + n)*OD + c],
                    g_pmax[((b*2 + 1)*NN + n)*OD + c]);
    out_msgs[bn*OD + c] = m;
    ms[c] = m;
    __syncthreads();
    float acc = g_zU1[bn*OD + c];
    #pragma unroll 4
    for (int k = 0; k < 128; k++) acc += ms[k]*WU2[k*OD + c];
    float s = acc;
    #pragma unroll
    for (int off = 16; off > 0; off >>= 1) s += __shfl_xor_sync(0xffffffffu, s, off);
    if (l == 0) red[w] = s;
    __syncthreads();
    float mean = (red[0] + red[1] + red[2] + red[3]) * 0.0078125f;
    float d = acc - mean;
    float q = d*d;
    #pragma unroll
    for (int off = 16; off > 0; off >>= 1) q += __shfl_xor_sync(0xffffffffu, q, off);
    __syncthreads();
    if (l == 0) red[w] = q;
    __syncthreads();
    float var = (red[0] + red[1] + red[2] + red[3]) * 0.0078125f;
    out_ret[bn*OD + c] = fmaf(lnfs[c]*rsqrtf(var + EPSV), d, lnfo[c]);
}

extern "C" void kernel_launch(void* const* d_in, const int* in_sizes, int n_in,
                              void* d_out, int out_size) {
    const float* z    = (const float*)d_in[0];
    const float* e    = (const float*)d_in[1];
    const float* gf   = (const float*)d_in[2];
    const void*  maskp= d_in[3];
    const void*  adjp = d_in[4];
    const float* Wt1  = (const float*)d_in[5];
    const float* Wt2  = (const float*)d_in[6];
    const float* Wt3  = (const float*)d_in[7];
    const float* We1  = (const float*)d_in[8];
    const float* We2  = (const float*)d_in[9];
    const float* We3  = (const float*)d_in[10];
    const float* Wg   = (const float*)d_in[11];
    const float* Wm1  = (const float*)d_in[12];
    const float* Wm2  = (const float*)d_in[13];
    const float* Wme  = (const float*)d_in[14];
    const float* Wmg  = (const float*)d_in[15];
    const float* ln1s = (const float*)d_in[16];
    const float* ln1o = (const float*)d_in[17];
    const float* Wmlp1= (const float*)d_in[18];
    const float* ln2s = (const float*)d_in[19];
    const float* ln2o = (const float*)d_in[20];
    const float* Wmlp2= (const float*)d_in[21];
    const float* WU1  = (const float*)d_in[22];
    const float* WU2  = (const float*)d_in[23];
    const float* WU3  = (const float*)d_in[24];
    const float* lnfs = (const float*)d_in[25];
    const float* lnfo = (const float*)d_in[26];

    float* out      = (float*)d_out;
    float* out_ret  = out;                 // (B,N,OUT)
    float* out_msgs = out + BB*NN*OD;      // (B,N,OUT)
    float* out_tri  = out + 2*BB*NN*OD;    // (B,N,N,OUT)

    cudaFuncSetAttribute(k_node, cudaFuncAttributeMaxDynamicSharedMemorySize,
                         NODE_SMEM_FLOATS*4);
    cudaFuncSetAttribute(k_trimax, cudaFuncAttributeMaxDynamicSharedMemorySize,
                         TRI_SMEM_FLOATS*4);
    cudaFuncSetAttribute(k_pair, cudaFuncAttributeMaxDynamicSharedMemorySize,
                         PAIR_SMEM_FLOATS*4);

    // slot 4 (the profiled one) = k_pair, verifying the 512-thread variant.
    k_convbool<<<64, 256>>>(maskp, adjp);
    k_graph<<<BB, 128>>>(gf, Wg, Wmg);
    k_node<<<BB*NN/4, 512, NODE_SMEM_FLOATS*4>>>(z, Wm1, Wm2, WU1, Wt1, Wt2, Wt3);
    k_pair<<<dim3(16,2,BB), 512, PAIR_SMEM_FLOATS*4>>>(e, Wme, Wmlp1, Wmlp2,
                                                       ln1s, ln1o, ln2s, ln2o);
    k_eproj<<<BB*NN*NN/64, 256>>>(e, We1, We2, We3);
    k_trimax<<<dim3(16,16,BB), 512, TRI_SMEM_FLOATS*4>>>(WU3, out_tri);
    k_final<<<BB*NN, 128>>>(WU2, lnfs, lnfo, out_ret, out_msgs);
}

// round 16
// speedup vs baseline: 1.0776x; 1.0776x over previous
#include <cuda_runtime.h>

#define BB 4
#define NN 128
#define IND 256
#define OD 128
#define NEGV (-1.0e9f)
#define EPSV (1e-5f)

// ---------------- scratch (device globals; no allocation) ----------------
__device__ __align__(16) float g_tri1[BB*NN*8];
__device__ __align__(16) float g_tri2[BB*NN*8];
__device__ __align__(16) float g_tri3[BB*NN*8];
__device__ __align__(16) float g_trig[BB*8];
__device__ __align__(16) float g_msgg[BB*OD];
__device__ __align__(16) float g_msg1[BB*NN*OD];
__device__ __align__(16) float g_msg2[BB*NN*OD];
__device__ __align__(16) float g_zU1[BB*NN*OD];
__device__ __align__(16) float g_e1t[BB*NN*NN*8];   // [b][j][i][c]
__device__ __align__(16) float g_e2t[BB*NN*NN*8];   // [b][k][i][c]
__device__ __align__(16) float g_e3n[BB*NN*NN*8];   // [b][j][k][c]
__device__ __align__(16) float g_pmax[BB*2*NN*OD];  // [b][ihalf][j][c]
__device__ unsigned char g_mask[BB*NN];
__device__ unsigned char g_adj[BB*NN*NN];

// order-preserving float<->uint for atomicMax
__device__ __forceinline__ unsigned fkey(float f) {
    unsigned b = __float_as_uint(f);
    return (b & 0x80000000u) ? ~b : (b | 0x80000000u);
}
__device__ __forceinline__ float fdec(unsigned k) {
    return __uint_as_float((k & 0x80000000u) ? (k & 0x7fffffffu) : ~k);
}

// ---------------- bool-dtype detection + canonicalization (parallel) ----------------
__global__ void __launch_bounds__(256) k_convbool(const void* maskp, const void* adjp) {
    __shared__ unsigned sf[8], sg[8];
    int t = threadIdx.x, bi = blockIdx.x, w = t >> 5;
    unsigned f = 0, g = 0;
    const unsigned* aw = (const unsigned*)adjp;
    for (int i = t; i < 16384; i += 256) {
        unsigned v = aw[i];
        f |= (v == 0x3F800000u);
        g |= (v > 1u && v != 0x3F800000u);
    }
    f = __any_sync(0xffffffffu, f);
    g = __any_sync(0xffffffffu, g);
    if ((t & 31) == 0) { sf[w] = f; sg[w] = g; }
    __syncthreads();
    unsigned F = sf[0]|sf[1]|sf[2]|sf[3]|sf[4]|sf[5]|sf[6]|sf[7];
    unsigned G = sg[0]|sg[1]|sg[2]|sg[3]|sg[4]|sg[5]|sg[6]|sg[7];
    int cls = F ? 2 : (G ? 0 : 1);  // 0=u8, 1=i32, 2=f32
    int base = bi*1024;
    if (cls == 0) {
        const unsigned char* a = (const unsigned char*)adjp;
        const unsigned char* m = (const unsigned char*)maskp;
        for (int i = t; i < 1024; i += 256) g_adj[base+i] = a[base+i] ? 1 : 0;
        if (t < 8) g_mask[bi*8+t] = m[bi*8+t] ? 1 : 0;
    } else if (cls == 1) {
        const int* a = (const int*)adjp;
        const int* m = (const int*)maskp;
        for (int i = t; i < 1024; i += 256) g_adj[base+i] = a[base+i] ? 1 : 0;
        if (t < 8) g_mask[bi*8+t] = m[bi*8+t] ? 1 : 0;
    } else {
        const float* a = (const float*)adjp;
        const float* m = (const float*)maskp;
        for (int i = t; i < 1024; i += 256) g_adj[base+i] = (a[base+i] != 0.0f) ? 1 : 0;
        if (t < 8) g_mask[bi*8+t] = (m[bi*8+t] != 0.0f) ? 1 : 0;
    }
}

// ---------------- graph projections ----------------
__global__ void __launch_bounds__(128) k_graph(const float* __restrict__ gf,
                                               const float* __restrict__ Wg,
                                               const float* __restrict__ Wmg) {
    int b = blockIdx.x, c = threadIdx.x;
    __shared__ float gs[IND/2];
    gs[c] = gf[b*(IND/2) + c];
    __syncthreads();
    float acc = 0.f;
    #pragma unroll 4
    for (int k = 0; k < IND/2; k++) acc += gs[k]*Wmg[k*OD + c];
    g_msgg[b*OD + c] = acc;
    if (c < 8) {
        float a = 0.f;
        for (int k = 0; k < IND/2; k++) a += gs[k]*Wg[k*8 + c];
        g_trig[b*8 + c] = a;
    }
}

// ---------------- node projections: smem-staged GEMM, 512 threads ----------------
#define NODE_SMEM_FLOATS 19648
__global__ void __launch_bounds__(512,2) k_node(const float* __restrict__ z,
                                                const float* __restrict__ Wm1,
                                                const float* __restrict__ Wm2,
                                                const float* __restrict__ WU1,
                                                const float* __restrict__ Wt1,
                                                const float* __restrict__ Wt2,
                                                const float* __restrict__ Wt3) {
    extern __shared__ float smn[];
    float* zs   = smn;          // 4*256
    float* Wts  = smn + 1024;   // 256*24
    float* Wc   = smn + 7168;   // 3*32*128
    float* ptri = smn + 19456;  // 192
    int r0 = blockIdx.x*4, t = threadIdx.x;
    int c = t & 127, h = t >> 7;

    {
        float4* zs4 = (float4*)zs;
        const float4* zsrc = (const float4*)(z + (long)r0*IND);
        for (int i = t; i < 256; i += 512) zs4[i] = zsrc[i];
    }
    for (int i = t; i < 2048; i += 512) {
        int k = i >> 3, cc = i & 7;
        Wts[k*24 + cc]      = Wt1[i];
        Wts[k*24 + 8 + cc]  = Wt2[i];
        Wts[k*24 + 16 + cc] = Wt3[i];
    }

    float a1 = 0.f, a2 = 0.f, a3 = 0.f;
    for (int kc = 0; kc < 8; kc++) {
        int k0 = kc*32;
        __syncthreads();
        {
            const float4* s1 = (const float4*)(Wm1 + k0*OD);
            const float4* s2 = (const float4*)(Wm2 + k0*OD);
            const float4* s3 = (const float4*)(WU1 + k0*OD);
            float4* d = (float4*)Wc;
            for (int i = t; i < 1024; i += 512) {
                d[i] = s1[i]; d[1024 + i] = s2[i]; d[2048 + i] = s3[i];
            }
        }
        __syncthreads();
        const float* W1s = Wc, *W2s = Wc + 4096, *W3s = Wc + 8192;
        const float* zp = zs + h*IND + k0;
        #pragma unroll 8
        for (int k = 0; k < 32; k++) {
            float w1 = W1s[k*128 + c], w2 = W2s[k*128 + c], w3 = W3s[k*128 + c];
            float zv = zp[k];
            a1 += zv*w1; a2 += zv*w2; a3 += zv*w3;
        }
    }
    {
        int bn = r0 + h;
        float mk = g_mask[bn] ? 1.0f : 0.0f;
        g_msg1[bn*OD + c] = a1*mk;
        g_msg2[bn*OD + c] = a2*mk;
        g_zU1[bn*OD + c]  = a3;
    }
    if (t < 192) {
        int rr = t/48, rem = t%48, q = rem >> 1, kh = rem & 1;
        float s = 0.f;
        const float* zr = zs + rr*IND + kh*128;
        const float* wq = Wts + (kh*128)*24 + q;
        #pragma unroll 8
        for (int k = 0; k < 128; k++) s += zr[k]*wq[k*24];
        ptri[t] = s;
    }
    __syncthreads();
    if (t < 96) {
        int rr = t/24, q = t%24;
        float s = ptri[rr*48 + q*2] + ptri[rr*48 + q*2 + 1];
        int bn = r0 + rr;
        s *= (g_mask[bn] ? 1.0f : 0.0f);
        int cc = q & 7;
        if (q < 8)       g_tri1[bn*8 + cc] = s;
        else if (q < 16) g_tri2[bn*8 + cc] = s;
        else             g_tri3[bn*8 + cc] = s;
    }
}

// ---------------- edge projections: warp-uniform q, broadcast weights ----------------
__global__ void __launch_bounds__(256) k_eproj(const float* __restrict__ e,
                                               const float* __restrict__ We1,
                                               const float* __restrict__ We2,
                                               const float* __restrict__ We3) {
    __shared__ float Ws[128*32];   // [k][32]: q*8 + (0..5) used
    __shared__ float es[64*132];   // [r]: 33 float4 per row (pad)
    int t = threadIdx.x;
    for (int idx = t; idx < 128*24; idx += 256) {
        int k = idx/24, r = idx%24;
        float v;
        if (r < 8)       v = We1[k*8 + r];
        else if (r < 16) v = We2[k*8 + (r-8)];
        else             v = We3[k*8 + (r-16)];
        Ws[k*32 + (r/6)*8 + (r%6)] = v;
    }
    long row0 = (long)blockIdx.x*64;
    const float4* esrc = (const float4*)(e + row0*128);
    float4* es4 = (float4*)es;
    for (int idx = t; idx < 2048; idx += 256) {
        int r = idx >> 5, kq = idx & 31;
        es4[r*33 + kq] = esrc[idx];
    }
    __syncthreads();
    int r = t & 63, q = t >> 6;      // q warp-uniform -> weight LDS broadcast
    float acc[6] = {0,0,0,0,0,0};
    const float4* erow4 = es4 + r*33;
    const float* wb = Ws + q*8;
    #pragma unroll 2
    for (int k4 = 0; k4 < 32; k4++) {
        float4 ev = erow4[k4];
        #pragma unroll
        for (int kk = 0; kk < 4; kk++) {
            int k = k4*4 + kk;
            float4 w0 = *(const float4*)(wb + k*32);
            float2 w1 = *(const float2*)(wb + k*32 + 4);
            float evk = (&ev.x)[kk];
            acc[0] += evk*w0.x; acc[1] += evk*w0.y; acc[2] += evk*w0.z;
            acc[3] += evk*w0.w; acc[4] += evk*w1.x; acc[5] += evk*w1.y;
        }
    }
    int row = (int)row0 + r;
    int b = row >> 14, r1 = (row >> 7) & 127, r2 = row & 127; // r1=i, r2=j(or k)
    int tidx = ((b*NN + r2)*NN + r1)*8;
    if (q == 0) {
        *(float4*)&g_e1t[tidx]   = make_float4(acc[0], acc[1], acc[2], acc[3]);
        *(float2*)&g_e1t[tidx+4] = make_float2(acc[4], acc[5]);
    } else if (q == 1) {
        *(float2*)&g_e1t[tidx+6] = make_float2(acc[0], acc[1]);
        *(float4*)&g_e2t[tidx]   = make_float4(acc[2], acc[3], acc[4], acc[5]);
    } else if (q == 2) {
        *(float4*)&g_e2t[tidx+4] = make_float4(acc[0], acc[1], acc[2], acc[3]);
        *(float2*)&g_e3n[row*8]  = make_float2(acc[4], acc[5]);
    } else {
        *(float2*)&g_e3n[row*8+2] = make_float2(acc[0], acc[1]);
        *(float4*)&g_e3n[row*8+4] = make_float4(acc[2], acc[3], acc[4], acc[5]);
    }
}

// ---------------- triplet max-plus core + @WU3 + relu (512thr, 2 blocks/SM) ----------------
#define TRI_SMEM_FLOATS 19352
__global__ void __launch_bounds__(512,2) k_trimax(const float* __restrict__ WU3,
                                                  float* __restrict__ out_tri) {
    extern __shared__ float sm[];
    float* A_s  = sm;            // 1024 (reused as partial buffer after S1+=A)
    float* S1   = sm + 1024;     // 8*1032 (tri1 + E1 fused)
    float* E2s  = sm + 9280;     // 8*1032
    float* pen  = sm + 17536;    // 128
    float* t2s  = sm + 17664;    // 64
    float* t3s  = sm + 17728;    // 64
    float* tgs  = sm + 17792;    // 8
    float* mjf  = sm + 17800;    // 8
    float* mkf  = sm + 17808;    // 8
    float* WU3s = sm + 17816;    // 1024
    float* Ps   = sm + 18840;    // 512
    float* Pp   = A_s;           // 256*4 partials (alias)

    int t = threadIdx.x;
    int jt = blockIdx.x, kt = blockIdx.y, b = blockIdx.z;
    int j0 = jt*8, k0 = kt*8;

    for (int idx = t; idx < 1024; idx += 512) {
        A_s[idx]  = g_tri1[b*1024 + idx];
        WU3s[idx] = WU3[idx];
    }
    {
        float4* S14 = (float4*)S1;
        float4* E24 = (float4*)E2s;
        for (int idx = t; idx < 2048; idx += 512) {
            int s = idx >> 8, r4 = idx & 255;
            S14[s*258 + r4] = ((const float4*)g_e1t)[((b*NN + j0 + s) << 8) + r4];
            E24[s*258 + r4] = ((const float4*)g_e2t)[((b*NN + k0 + s) << 8) + r4];
        }
    }
    if (t < 128) pen[t] = g_mask[b*NN + t] ? 0.0f : -2.0e9f;
    if (t >= 128 && t < 192) t2s[t-128] = g_tri2[b*1024 + j0*8 + (t-128)];
    if (t >= 192 && t < 256) t3s[t-192] = g_tri3[b*1024 + k0*8 + (t-192)];
    if (t >= 256 && t < 264) tgs[t-256] = g_trig[b*8 + (t-256)];
    if (t >= 264 && t < 272) mjf[t-264] = g_mask[b*NN + j0 + (t-264)] ? 1.0f : 0.0f;
    if (t >= 272 && t < 280) mkf[t-272] = g_mask[b*NN + k0 + (t-272)] ? 1.0f : 0.0f;
    __syncthreads();
    {   // S1 += A (broadcast over jj)
        float4* S14 = (float4*)S1;
        const float4* A4 = (const float4*)A_s;
        for (int idx = t; idx < 2048; idx += 512) {
            int s = idx >> 8, r4 = idx & 255;
            float4 v = S14[s*258 + r4], a = A4[r4];
            v.x += a.x; v.y += a.y; v.z += a.z; v.w += a.w;
            S14[s*258 + r4] = v;
        }
    }
    __syncthreads();

    int r = t & 255;
    int ih = t >> 8;             // i-half
    int jj = r >> 5;             // warp-uniform
    int kk = (r >> 2) & 7;
    int cp = (r & 3)*2;
    const float* s1p = S1 + jj*1032 + cp + ih*512;   // +64 i
    const float* e2p = E2s + kk*1032 + cp + ih*512;
    const float* penh = pen + ih*64;
    bool jv = (mjf[jj] != 0.0f);

    float a0a = NEGV, a0b = NEGV, a1a = NEGV, a1b = NEGV;
    float v0a = NEGV, v0b = NEGV, v1a = NEGV, v1b = NEGV;
    if (jv) {
        #pragma unroll 4
        for (int i = 0; i < 64; i += 2) {
            float2 sA = *(const float2*)(s1p + i*8);
            float2 eA = *(const float2*)(e2p + i*8);
            float2 sB = *(const float2*)(s1p + i*8 + 8);
            float2 eB = *(const float2*)(e2p + i*8 + 8);
            a0a = fmaxf(a0a, sA.x + eA.x); a1a = fmaxf(a1a, sA.y + eA.y);
            a0b = fmaxf(a0b, sB.x + eB.x); a1b = fmaxf(a1b, sB.y + eB.y);
        }
    } else {
        #pragma unroll 4
        for (int i = 0; i < 64; i += 2) {
            float2 sA = *(const float2*)(s1p + i*8);
            float2 eA = *(const float2*)(e2p + i*8);
            float2 sB = *(const float2*)(s1p + i*8 + 8);
            float2 eB = *(const float2*)(e2p + i*8 + 8);
            float pA = penh[i], pB = penh[i+1];
            float x0 = sA.x + eA.x, x1 = sA.y + eA.y;
            float y0 = sB.x + eB.x, y1 = sB.y + eB.y;
            a0a = fmaxf(a0a, x0); a1a = fmaxf(a1a, x1);
            a0b = fmaxf(a0b, y0); a1b = fmaxf(a1b, y1);
            v0a = fmaxf(v0a, x0 + pA); v1a = fmaxf(v1a, x1 + pA);
            v0b = fmaxf(v0b, y0 + pB); v1b = fmaxf(v1b, y1 + pB);
        }
    }
    float mA0 = fmaxf(a0a, a0b), mA1 = fmaxf(a1a, a1b);
    float mV0 = fmaxf(v0a, v0b), mV1 = fmaxf(v1a, v1b);

    __syncthreads();   // A_s reads all done; safe to alias as Pp
    if (ih == 1) {
        float4* pp = (float4*)(Pp + r*4);
        *pp = make_float4(mA0, mA1, mV0, mV1);
    }
    __syncthreads();
    if (ih == 0) {
        float4 o = *(const float4*)(Pp + r*4);
        mA0 = fmaxf(mA0, o.x); mA1 = fmaxf(mA1, o.y);
        mV0 = fmaxf(mV0, o.z); mV1 = fmaxf(mV1, o.w);
        bool cond = jv || (mkf[kk] != 0.0f);
        int jg = j0 + jj, kg = k0 + kk;
        float2 e3v = *(const float2*)&g_e3n[((b*NN + jg)*NN + kg)*8 + cp];
        float base0 = t2s[jj*8 + cp]     + t3s[kk*8 + cp]     + tgs[cp]     + e3v.x;
        float base1 = t2s[jj*8 + cp + 1] + t3s[kk*8 + cp + 1] + tgs[cp + 1] + e3v.y;
        float p0 = cond ? (mA0 + base0) : fmaxf(mV0 + base0, NEGV);
        float p1 = cond ? (mA1 + base1) : fmaxf(mV1 + base1, NEGV);
        *(float2*)&Ps[(jj*8 + kk)*8 + cp] = make_float2(p0, p1);
    }
    __syncthreads();

    #pragma unroll
    for (int oi = 0; oi < 16; oi++) {
        int idx = t + 512*oi;
        int jk = idx >> 7, o = idx & 127;
        const float* pr = Ps + jk*8;
        float acc = 0.f;
        #pragma unroll
        for (int c = 0; c < 8; c++) acc += pr[c]*WU3s[c*128 + o];
        acc = fmaxf(acc, 0.0f);
        int jjx = jk >> 3, kkx = jk & 7;
        out_tri[(((long)b*NN + j0 + jjx)*NN + (k0 + kkx))*OD + o] = acc;
    }
}

// ---------------- fused pairwise MLP + masked max over i (R7 version, 78us) ----------------
__device__ __forceinline__ void ln_relu4(float* x, float4 s, float4 o) {
    float sum = x[0] + x[1] + x[2] + x[3];
    #pragma unroll
    for (int off = 16; off > 0; off >>= 1) sum += __shfl_xor_sync(0xffffffffu, sum, off);
    float mean = sum * 0.0078125f;
    float d0 = x[0]-mean, d1 = x[1]-mean, d2 = x[2]-mean, d3 = x[3]-mean;
    float q = d0*d0 + d1*d1 + d2*d2 + d3*d3;
    #pragma unroll
    for (int off = 16; off > 0; off >>= 1) q += __shfl_xor_sync(0xffffffffu, q, off);
    float rs = rsqrtf(q*0.0078125f + EPSV);
    x[0] = fmaxf(fmaf(s.x*rs, d0, o.x), 0.f);
    x[1] = fmaxf(fmaf(s.y*rs, d1, o.y), 0.f);
    x[2] = fmaxf(fmaf(s.z*rs, d2, o.z), 0.f);
    x[3] = fmaxf(fmaf(s.w*rs, d3, o.w), 0.f);
}

__device__ __forceinline__ void gemv6(const float* eb, const float4* W4, int l,
                                      float a[6][4]) {
    #pragma unroll 2
    for (int k4 = 0; k4 < 32; k4++) {
        float4 v[6];
        #pragma unroll
        for (int q = 0; q < 6; q++) v[q] = ((const float4*)(eb + q*128))[k4];
        #pragma unroll
        for (int kk = 0; kk < 4; kk++) {
            float4 wv = W4[(k4*4 + kk)*32 + l];
            #pragma unroll
            for (int q = 0; q < 6; q++) {
                float f = (&v[q].x)[kk];
                a[q][0] += f*wv.x; a[q][1] += f*wv.y;
                a[q][2] += f*wv.z; a[q][3] += f*wv.w;
            }
        }
    }
}

#define PAIR_SMEM_FLOATS 56864
__global__ void __launch_bounds__(256,1) k_pair(
    const float* __restrict__ e,
    const float* __restrict__ Wme, const float* __restrict__ Wmlp1, const float* __restrict__ Wmlp2,
    const float* __restrict__ ln1s, const float* __restrict__ ln1o,
    const float* __restrict__ ln2s, const float* __restrict__ ln2o) {
    extern __shared__ float sm[];
    float* Wme_s = sm;
    float* W1_s  = sm + 16384;
    float* W2_s  = sm + 32768;
    float* ebuf  = sm + 49152;               // 8 warps * 6 rows * 128
    int*   lists = (int*)(sm + 55296);       // 8 cols * 64
    unsigned* smax = (unsigned*)(sm + 55808); // 8 cols * 128
    int*   offs  = (int*)(sm + 56832);       // 17

    int t = threadIdx.x, w = t >> 5, l = t & 31;
    int jt = blockIdx.x, half = blockIdx.y, b = blockIdx.z;

    {
        const float4* a  = (const float4*)Wme;
        const float4* c1 = (const float4*)Wmlp1;
        const float4* c2 = (const float4*)Wmlp2;
        float4* d0 = (float4*)Wme_s; float4* d1 = (float4*)W1_s; float4* d2 = (float4*)W2_s;
        for (int idx = t; idx < 4096; idx += 256) { d0[idx] = a[idx]; d1[idx] = c1[idx]; d2[idx] = c2[idx]; }
    }
    unsigned negkey = fkey(NEGV);
    for (int idx = t; idx < 1024; idx += 256) smax[idx] = negkey;

    int jw = jt*8 + w;
    int* list = lists + w*64;
    int cnt = 0;
    for (int base = 0; base < 64; base += 32) {
        int i = half*64 + base + l;
        int f = g_adj[(b*NN + i)*NN + jw] ? 1 : 0;
        unsigned bal = __ballot_sync(0xffffffffu, f);
        int pos = cnt + __popc(bal & ((1u << l) - 1u));
        if (f) list[pos] = i;
        cnt += __popc(bal);
    }
    if (l == 0) offs[9 + w] = cnt;
    __syncthreads();
    if (t == 0) {
        int s = 0;
        #pragma unroll
        for (int q = 0; q < 8; q++) { offs[q] = s; s += offs[9 + q]; }
        offs[8] = s;
    }
    __syncthreads();
    int E = offs[8];

    int c0 = 4*l;
    float4 mgg = *(const float4*)&g_msgg[b*OD + c0];
    float4 p1s = *(const float4*)&ln1s[c0];
    float4 p1o = *(const float4*)&ln1o[c0];
    float4 p2s = *(const float4*)&ln2s[c0];
    float4 p2o = *(const float4*)&ln2o[c0];

    const float4* Wme4 = (const float4*)Wme_s;
    const float4* W14  = (const float4*)W1_s;
    const float4* W24  = (const float4*)W2_s;
    float* eb = ebuf + w*768;

    for (int g0 = w*6; g0 < E; g0 += 48) {
        int nv = E - g0; if (nv > 6) nv = 6;
        int id[6], jl[6];
        #pragma unroll
        for (int q = 0; q < 6; q++) {
            int fi = g0 + (q < nv ? q : nv-1);
            int c = 0;
            #pragma unroll
            for (int x = 1; x < 8; x++) if (fi >= offs[x]) c = x;
            jl[q] = c;
            id[q] = lists[c*64 + fi - offs[c]];
        }
        float a[6][4];
        #pragma unroll
        for (int q = 0; q < 6; q++) {
            int jq = jt*8 + jl[q];
            float4 m1 = *(const float4*)&g_msg1[(b*NN + jq)*OD + c0];
            float4 m2 = *(const float4*)&g_msg2[(b*NN + id[q])*OD + c0];
            a[q][0] = m1.x + m2.x + mgg.x; a[q][1] = m1.y + m2.y + mgg.y;
            a[q][2] = m1.z + m2.z + mgg.z; a[q][3] = m1.w + m2.w + mgg.w;
        }
        __syncwarp();
        #pragma unroll
        for (int q = 0; q < 6; q++) {
            int jq = jt*8 + jl[q];
            ((float4*)(eb + q*128))[l] = *(const float4*)&e[(((long)b*NN + id[q])*NN + jq)*128 + c0];
        }
        __syncwarp();

        gemv6(eb, Wme4, l, a);
        #pragma unroll
        for (int q = 0; q < 6; q++) ln_relu4(a[q], p1s, p1o);
        __syncwarp();
        #pragma unroll
        for (int q = 0; q < 6; q++)
            ((float4*)(eb + q*128))[l] = make_float4(a[q][0], a[q][1], a[q][2], a[q][3]);
        __syncwarp();

        float a2[6][4];
        #pragma unroll
        for (int q = 0; q < 6; q++) { a2[q][0]=0; a2[q][1]=0; a2[q][2]=0; a2[q][3]=0; }
        gemv6(eb, W14, l, a2);
        #pragma unroll
        for (int q = 0; q < 6; q++) ln_relu4(a2[q], p2s, p2o);
        __syncwarp();
        #pragma unroll
        for (int q = 0; q < 6; q++)
            ((float4*)(eb + q*128))[l] = make_float4(a2[q][0], a2[q][1], a2[q][2], a2[q][3]);
        __syncwarp();

        float a3[6][4];
        #pragma unroll
        for (int q = 0; q < 6; q++) { a3[q][0]=0; a3[q][1]=0; a3[q][2]=0; a3[q][3]=0; }
        gemv6(eb, W24, l, a3);
        #pragma unroll
        for (int q = 0; q < 6; q++) {
            if (q < nv) {
                unsigned* sj = smax + jl[q]*128 + c0;
                atomicMax(&sj[0], fkey(a3[q][0]));
                atomicMax(&sj[1], fkey(a3[q][1]));
                atomicMax(&sj[2], fkey(a3[q][2]));
                atomicMax(&sj[3], fkey(a3[q][3]));
            }
        }
    }
    __syncthreads();
    for (int idx = t; idx < 1024; idx += 256) {
        int jl2 = idx >> 7, c = idx & 127;
        g_pmax[((b*2 + half)*NN + jt*8 + jl2)*OD + c] = fdec(smax[idx]);
    }
}

// ---------------- final: msgs out + ret = LN(zU1 + msgs@WU2) ----------------
__global__ void __launch_bounds__(128) k_final(const float* __restrict__ WU2,
                                               const float* __restrict__ lnfs,
                                               const float* __restrict__ lnfo,
                                               float* __restrict__ out_ret,
                                               float* __restrict__ out_msgs) {
    int bn = blockIdx.x;
    int b = bn >> 7;
    int c = threadIdx.x, l = c & 31, w = c >> 5;
    int n = bn & 127;
    __shared__ float ms[128];
    __shared__ float red[4];
    float m = fmaxf(g_pmax[((b*2 + 0)*NN + n)*OD + c],
                    g_pmax[((b*2 + 1)*NN + n)*OD + c]);
    out_msgs[bn*OD + c] = m;
    ms[c] = m;
    __syncthreads();
    float acc = g_zU1[bn*OD + c];
    #pragma unroll 4
    for (int k = 0; k < 128; k++) acc += ms[k]*WU2[k*OD + c];
    float s = acc;
    #pragma unroll
    for (int off = 16; off > 0; off >>= 1) s += __shfl_xor_sync(0xffffffffu, s, off);
    if (l == 0) red[w] = s;
    __syncthreads();
    float mean = (red[0] + red[1] + red[2] + red[3]) * 0.0078125f;
    float d = acc - mean;
    float q = d*d;
    #pragma unroll
    for (int off = 16; off > 0; off >>= 1) q += __shfl_xor_sync(0xffffffffu, q, off);
    __syncthreads();
    if (l == 0) red[w] = q;
    __syncthreads();
    float var = (red[0] + red[1] + red[2] + red[3]) * 0.0078125f;
    out_ret[bn*OD + c] = fmaf(lnfs[c]*rsqrtf(var + EPSV), d, lnfo[c]);
}

extern "C" void kernel_launch(void* const* d_in, const int* in_sizes, int n_in,
                              void* d_out, int out_size) {
    const float* z    = (const float*)d_in[0];
    const float* e    = (const float*)d_in[1];
    const float* gf   = (const float*)d_in[2];
    const void*  maskp= d_in[3];
    const void*  adjp = d_in[4];
    const float* Wt1  = (const float*)d_in[5];
    const float* Wt2  = (const float*)d_in[6];
    const float* Wt3  = (const float*)d_in[7];
    const float* We1  = (const float*)d_in[8];
    const float* We2  = (const float*)d_in[9];
    const float* We3  = (const float*)d_in[10];
    const float* Wg   = (const float*)d_in[11];
    const float* Wm1  = (const float*)d_in[12];
    const float* Wm2  = (const float*)d_in[13];
    const float* Wme  = (const float*)d_in[14];
    const float* Wmg  = (const float*)d_in[15];
    const float* ln1s = (const float*)d_in[16];
    const float* ln1o = (const float*)d_in[17];
    const float* Wmlp1= (const float*)d_in[18];
    const float* ln2s = (const float*)d_in[19];
    const float* ln2o = (const float*)d_in[20];
    const float* Wmlp2= (const float*)d_in[21];
    const float* WU1  = (const float*)d_in[22];
    const float* WU2  = (const float*)d_in[23];
    const float* WU3  = (const float*)d_in[24];
    const float* lnfs = (const float*)d_in[25];
    const float* lnfo = (const float*)d_in[26];

    float* out      = (float*)d_out;
    float* out_ret  = out;                 // (B,N,OUT)
    float* out_msgs = out + BB*NN*OD;      // (B,N,OUT)
    float* out_tri  = out + 2*BB*NN*OD;    // (B,N,N,OUT)

    cudaFuncSetAttribute(k_node, cudaFuncAttributeMaxDynamicSharedMemorySize,
                         NODE_SMEM_FLOATS*4);
    cudaFuncSetAttribute(k_trimax, cudaFuncAttributeMaxDynamicSharedMemorySize,
                         TRI_SMEM_FLOATS*4);
    cudaFuncSetAttribute(k_pair, cudaFuncAttributeMaxDynamicSharedMemorySize,
                         PAIR_SMEM_FLOATS*4);

    // slot 4 (the profiled one) = k_eproj, verifying the broadcast-weight map.
    k_convbool<<<64, 256>>>(maskp, adjp);
    k_graph<<<BB, 128>>>(gf, Wg, Wmg);
    k_node<<<BB*NN/4, 512, NODE_SMEM_FLOATS*4>>>(z, Wm1, Wm2, WU1, Wt1, Wt2, Wt3);
    k_eproj<<<BB*NN*NN/64, 256>>>(e, We1, We2, We3);
    k_trimax<<<dim3(16,16,BB), 512, TRI_SMEM_FLOATS*4>>>(WU3, out_tri);
    k_pair<<<dim3(16,2,BB), 256, PAIR_SMEM_FLOATS*4>>>(e, Wme, Wmlp1, Wmlp2,
                                                       ln1s, ln1o, ln2s, ln2o);
    k_final<<<BB*NN, 128>>>(WU2, lnfs, lnfo, out_ret, out_msgs);
}

// round 17
// speedup vs baseline: 1.1368x; 1.0549x over previous
#include <cuda_runtime.h>

#define BB 4
#define NN 128
#define IND 256
#define OD 128
#define NEGV (-1.0e9f)
#define EPSV (1e-5f)

// f32x2 helpers (PTX-only dual-FMA; each half is an exact RN fma)
#define PK2DUP(d, f) asm("mov.b64 %0, {%1, %1};" : "=l"(d) : "r"(__float_as_uint(f)))
#define PK2(d, lo, hi) asm("mov.b64 %0, {%1, %2};" : "=l"(d) : "r"(__float_as_uint(lo)), "r"(__float_as_uint(hi)))
#define UPK2(lo, hi, d) { unsigned _ul, _uh; asm("mov.b64 {%0, %1}, %2;" : "=r"(_ul), "=r"(_uh) : "l"(d)); lo = __uint_as_float(_ul); hi = __uint_as_float(_uh); }
#define FMA2(d, a, b, c) asm("fma.rn.f32x2 %0, %1, %2, %3;" : "=l"(d) : "l"(a), "l"(b), "l"(c))

// ---------------- scratch (device globals; no allocation) ----------------
__device__ __align__(16) float g_tri1[BB*NN*8];
__device__ __align__(16) float g_tri2[BB*NN*8];
__device__ __align__(16) float g_tri3[BB*NN*8];
__device__ __align__(16) float g_trig[BB*8];
__device__ __align__(16) float g_msgg[BB*OD];
__device__ __align__(16) float g_msg1[BB*NN*OD];
__device__ __align__(16) float g_msg2[BB*NN*OD];
__device__ __align__(16) float g_zU1[BB*NN*OD];
__device__ __align__(16) float g_e1t[BB*NN*NN*8];   // [b][j][i][c]
__device__ __align__(16) float g_e2t[BB*NN*NN*8];   // [b][k][i][c]
__device__ __align__(16) float g_e3n[BB*NN*NN*8];   // [b][j][k][c]
__device__ __align__(16) float g_pmax[BB*2*NN*OD];  // [b][ihalf][j][c]
__device__ unsigned char g_mask[BB*NN];
__device__ unsigned char g_adj[BB*NN*NN];

// order-preserving float<->uint for atomicMax
__device__ __forceinline__ unsigned fkey(float f) {
    unsigned b = __float_as_uint(f);
    return (b & 0x80000000u) ? ~b : (b | 0x80000000u);
}
__device__ __forceinline__ float fdec(unsigned k) {
    return __uint_as_float((k & 0x80000000u) ? (k & 0x7fffffffu) : ~k);
}

// ---------------- bool-dtype detection + canonicalization (parallel) ----------------
__global__ void __launch_bounds__(256) k_convbool(const void* maskp, const void* adjp) {
    __shared__ unsigned sf[8], sg[8];
    int t = threadIdx.x, bi = blockIdx.x, w = t >> 5;
    unsigned f = 0, g = 0;
    const unsigned* aw = (const unsigned*)adjp;
    for (int i = t; i < 16384; i += 256) {
        unsigned v = aw[i];
        f |= (v == 0x3F800000u);
        g |= (v > 1u && v != 0x3F800000u);
    }
    f = __any_sync(0xffffffffu, f);
    g = __any_sync(0xffffffffu, g);
    if ((t & 31) == 0) { sf[w] = f; sg[w] = g; }
    __syncthreads();
    unsigned F = sf[0]|sf[1]|sf[2]|sf[3]|sf[4]|sf[5]|sf[6]|sf[7];
    unsigned G = sg[0]|sg[1]|sg[2]|sg[3]|sg[4]|sg[5]|sg[6]|sg[7];
    int cls = F ? 2 : (G ? 0 : 1);  // 0=u8, 1=i32, 2=f32
    int base = bi*1024;
    if (cls == 0) {
        const unsigned char* a = (const unsigned char*)adjp;
        const unsigned char* m = (const unsigned char*)maskp;
        for (int i = t; i < 1024; i += 256) g_adj[base+i] = a[base+i] ? 1 : 0;
        if (t < 8) g_mask[bi*8+t] = m[bi*8+t] ? 1 : 0;
    } else if (cls == 1) {
        const int* a = (const int*)adjp;
        const int* m = (const int*)maskp;
        for (int i = t; i < 1024; i += 256) g_adj[base+i] = a[base+i] ? 1 : 0;
        if (t < 8) g_mask[bi*8+t] = m[bi*8+t] ? 1 : 0;
    } else {
        const float* a = (const float*)adjp;
        const float* m = (const float*)maskp;
        for (int i = t; i < 1024; i += 256) g_adj[base+i] = (a[base+i] != 0.0f) ? 1 : 0;
        if (t < 8) g_mask[bi*8+t] = (m[bi*8+t] != 0.0f) ? 1 : 0;
    }
}

// ---------------- graph projections ----------------
__global__ void __launch_bounds__(128) k_graph(const float* __restrict__ gf,
                                               const float* __restrict__ Wg,
                                               const float* __restrict__ Wmg) {
    int b = blockIdx.x, c = threadIdx.x;
    __shared__ float gs[IND/2];
    gs[c] = gf[b*(IND/2) + c];
    __syncthreads();
    float acc = 0.f;
    #pragma unroll 4
    for (int k = 0; k < IND/2; k++) acc += gs[k]*Wmg[k*OD + c];
    g_msgg[b*OD + c] = acc;
    if (c < 8) {
        float a = 0.f;
        for (int k = 0; k < IND/2; k++) a += gs[k]*Wg[k*8 + c];
        g_trig[b*8 + c] = a;
    }
}

// ---------------- node projections: smem-staged GEMM, 512 threads ----------------
#define NODE_SMEM_FLOATS 19648
__global__ void __launch_bounds__(512,2) k_node(const float* __restrict__ z,
                                                const float* __restrict__ Wm1,
                                                const float* __restrict__ Wm2,
                                                const float* __restrict__ WU1,
                                                const float* __restrict__ Wt1,
                                                const float* __restrict__ Wt2,
                                                const float* __restrict__ Wt3) {
    extern __shared__ float smn[];
    float* zs   = smn;          // 4*256
    float* Wts  = smn + 1024;   // 256*24
    float* Wc   = smn + 7168;   // 3*32*128
    float* ptri = smn + 19456;  // 192
    int r0 = blockIdx.x*4, t = threadIdx.x;
    int c = t & 127, h = t >> 7;

    {
        float4* zs4 = (float4*)zs;
        const float4* zsrc = (const float4*)(z + (long)r0*IND);
        for (int i = t; i < 256; i += 512) zs4[i] = zsrc[i];
    }
    for (int i = t; i < 2048; i += 512) {
        int k = i >> 3, cc = i & 7;
        Wts[k*24 + cc]      = Wt1[i];
        Wts[k*24 + 8 + cc]  = Wt2[i];
        Wts[k*24 + 16 + cc] = Wt3[i];
    }

    float a1 = 0.f, a2 = 0.f, a3 = 0.f;
    for (int kc = 0; kc < 8; kc++) {
        int k0 = kc*32;
        __syncthreads();
        {
            const float4* s1 = (const float4*)(Wm1 + k0*OD);
            const float4* s2 = (const float4*)(Wm2 + k0*OD);
            const float4* s3 = (const float4*)(WU1 + k0*OD);
            float4* d = (float4*)Wc;
            for (int i = t; i < 1024; i += 512) {
                d[i] = s1[i]; d[1024 + i] = s2[i]; d[2048 + i] = s3[i];
            }
        }
        __syncthreads();
        const float* W1s = Wc, *W2s = Wc + 4096, *W3s = Wc + 8192;
        const float* zp = zs + h*IND + k0;
        #pragma unroll 8
        for (int k = 0; k < 32; k++) {
            float w1 = W1s[k*128 + c], w2 = W2s[k*128 + c], w3 = W3s[k*128 + c];
            float zv = zp[k];
            a1 += zv*w1; a2 += zv*w2; a3 += zv*w3;
        }
    }
    {
        int bn = r0 + h;
        float mk = g_mask[bn] ? 1.0f : 0.0f;
        g_msg1[bn*OD + c] = a1*mk;
        g_msg2[bn*OD + c] = a2*mk;
        g_zU1[bn*OD + c]  = a3;
    }
    if (t < 192) {
        int rr = t/48, rem = t%48, q = rem >> 1, kh = rem & 1;
        float s = 0.f;
        const float* zr = zs + rr*IND + kh*128;
        const float* wq = Wts + (kh*128)*24 + q;
        #pragma unroll 8
        for (int k = 0; k < 128; k++) s += zr[k]*wq[k*24];
        ptri[t] = s;
    }
    __syncthreads();
    if (t < 96) {
        int rr = t/24, q = t%24;
        float s = ptri[rr*48 + q*2] + ptri[rr*48 + q*2 + 1];
        int bn = r0 + rr;
        s *= (g_mask[bn] ? 1.0f : 0.0f);
        int cc = q & 7;
        if (q < 8)       g_tri1[bn*8 + cc] = s;
        else if (q < 16) g_tri2[bn*8 + cc] = s;
        else             g_tri3[bn*8 + cc] = s;
    }
}

// ---------------- edge projections: broadcast weights + f32x2 ----------------
__global__ void __launch_bounds__(256) k_eproj(const float* __restrict__ e,
                                               const float* __restrict__ We1,
                                               const float* __restrict__ We2,
                                               const float* __restrict__ We3) {
    __shared__ float Ws[128*32];   // [k][32]: q*8 + (0..5) used
    __shared__ float es[64*132];   // [r]: 33 float4 per row (pad)
    int t = threadIdx.x;
    for (int idx = t; idx < 128*24; idx += 256) {
        int k = idx/24, r = idx%24;
        float v;
        if (r < 8)       v = We1[k*8 + r];
        else if (r < 16) v = We2[k*8 + (r-8)];
        else             v = We3[k*8 + (r-16)];
        Ws[k*32 + (r/6)*8 + (r%6)] = v;
    }
    long row0 = (long)blockIdx.x*64;
    const float4* esrc = (const float4*)(e + row0*128);
    float4* es4 = (float4*)es;
    for (int idx = t; idx < 2048; idx += 256) {
        int r = idx >> 5, kq = idx & 31;
        es4[r*33 + kq] = esrc[idx];
    }
    __syncthreads();
    int r = t & 63, q = t >> 6;      // q warp-uniform -> weight LDS broadcast
    unsigned long long a01 = 0ull, a23 = 0ull, a45 = 0ull;
    const float4* erow4 = es4 + r*33;
    const float* wb = Ws + q*8;
    #pragma unroll 2
    for (int k4 = 0; k4 < 32; k4++) {
        float4 ev = erow4[k4];
        #pragma unroll
        for (int kk = 0; kk < 4; kk++) {
            int k = k4*4 + kk;
            ulonglong2 wp = *(const ulonglong2*)(wb + k*32);      // (w0,w1),(w2,w3)
            unsigned long long w45 = *(const unsigned long long*)(wb + k*32 + 4);
            float evk = (&ev.x)[kk];
            unsigned long long ff; PK2DUP(ff, evk);
            FMA2(a01, ff, wp.x, a01);
            FMA2(a23, ff, wp.y, a23);
            FMA2(a45, ff, w45, a45);
        }
    }
    float acc[6];
    UPK2(acc[0], acc[1], a01);
    UPK2(acc[2], acc[3], a23);
    UPK2(acc[4], acc[5], a45);
    int row = (int)row0 + r;
    int b = row >> 14, r1 = (row >> 7) & 127, r2 = row & 127; // r1=i, r2=j(or k)
    int tidx = ((b*NN + r2)*NN + r1)*8;
    if (q == 0) {
        *(float4*)&g_e1t[tidx]   = make_float4(acc[0], acc[1], acc[2], acc[3]);
        *(float2*)&g_e1t[tidx+4] = make_float2(acc[4], acc[5]);
    } else if (q == 1) {
        *(float2*)&g_e1t[tidx+6] = make_float2(acc[0], acc[1]);
        *(float4*)&g_e2t[tidx]   = make_float4(acc[2], acc[3], acc[4], acc[5]);
    } else if (q == 2) {
        *(float4*)&g_e2t[tidx+4] = make_float4(acc[0], acc[1], acc[2], acc[3]);
        *(float2*)&g_e3n[row*8]  = make_float2(acc[4], acc[5]);
    } else {
        *(float2*)&g_e3n[row*8+2] = make_float2(acc[0], acc[1]);
        *(float4*)&g_e3n[row*8+4] = make_float4(acc[2], acc[3], acc[4], acc[5]);
    }
}

// ---------------- triplet max-plus core + @WU3 + relu (512thr, 2 blocks/SM) ----------------
#define TRI_SMEM_FLOATS 19352
__global__ void __launch_bounds__(512,2) k_trimax(const float* __restrict__ WU3,
                                                  float* __restrict__ out_tri) {
    extern __shared__ float sm[];
    float* A_s  = sm;            // 1024 (reused as partial buffer after S1+=A)
    float* S1   = sm + 1024;     // 8*1032 (tri1 + E1 fused)
    float* E2s  = sm + 9280;     // 8*1032
    float* pen  = sm + 17536;    // 128
    float* t2s  = sm + 17664;    // 64
    float* t3s  = sm + 17728;    // 64
    float* tgs  = sm + 17792;    // 8
    float* mjf  = sm + 17800;    // 8
    float* mkf  = sm + 17808;    // 8
    float* WU3s = sm + 17816;    // 1024
    float* Ps   = sm + 18840;    // 512
    float* Pp   = A_s;           // 256*4 partials (alias)

    int t = threadIdx.x;
    int jt = blockIdx.x, kt = blockIdx.y, b = blockIdx.z;
    int j0 = jt*8, k0 = kt*8;

    for (int idx = t; idx < 1024; idx += 512) {
        A_s[idx]  = g_tri1[b*1024 + idx];
        WU3s[idx] = WU3[idx];
    }
    {
        float4* S14 = (float4*)S1;
        float4* E24 = (float4*)E2s;
        for (int idx = t; idx < 2048; idx += 512) {
            int s = idx >> 8, r4 = idx & 255;
            S14[s*258 + r4] = ((const float4*)g_e1t)[((b*NN + j0 + s) << 8) + r4];
            E24[s*258 + r4] = ((const float4*)g_e2t)[((b*NN + k0 + s) << 8) + r4];
        }
    }
    if (t < 128) pen[t] = g_mask[b*NN + t] ? 0.0f : -2.0e9f;
    if (t >= 128 && t < 192) t2s[t-128] = g_tri2[b*1024 + j0*8 + (t-128)];
    if (t >= 192 && t < 256) t3s[t-192] = g_tri3[b*1024 + k0*8 + (t-192)];
    if (t >= 256 && t < 264) tgs[t-256] = g_trig[b*8 + (t-256)];
    if (t >= 264 && t < 272) mjf[t-264] = g_mask[b*NN + j0 + (t-264)] ? 1.0f : 0.0f;
    if (t >= 272 && t < 280) mkf[t-272] = g_mask[b*NN + k0 + (t-272)] ? 1.0f : 0.0f;
    __syncthreads();
    {   // S1 += A (broadcast over jj)
        float4* S14 = (float4*)S1;
        const float4* A4 = (const float4*)A_s;
        for (int idx = t; idx < 2048; idx += 512) {
            int s = idx >> 8, r4 = idx & 255;
            float4 v = S14[s*258 + r4], a = A4[r4];
            v.x += a.x; v.y += a.y; v.z += a.z; v.w += a.w;
            S14[s*258 + r4] = v;
        }
    }
    __syncthreads();

    int r = t & 255;
    int ih = t >> 8;             // i-half
    int jj = r >> 5;             // warp-uniform
    int kk = (r >> 2) & 7;
    int cp = (r & 3)*2;
    const float* s1p = S1 + jj*1032 + cp + ih*512;   // +64 i
    const float* e2p = E2s + kk*1032 + cp + ih*512;
    const float* penh = pen + ih*64;
    bool jv = (mjf[jj] != 0.0f);

    float a0a = NEGV, a0b = NEGV, a1a = NEGV, a1b = NEGV;
    float v0a = NEGV, v0b = NEGV, v1a = NEGV, v1b = NEGV;
    if (jv) {
        #pragma unroll 4
        for (int i = 0; i < 64; i += 2) {
            float2 sA = *(const float2*)(s1p + i*8);
            float2 eA = *(const float2*)(e2p + i*8);
            float2 sB = *(const float2*)(s1p + i*8 + 8);
            float2 eB = *(const float2*)(e2p + i*8 + 8);
            a0a = fmaxf(a0a, sA.x + eA.x); a1a = fmaxf(a1a, sA.y + eA.y);
            a0b = fmaxf(a0b, sB.x + eB.x); a1b = fmaxf(a1b, sB.y + eB.y);
        }
    } else {
        #pragma unroll 4
        for (int i = 0; i < 64; i += 2) {
            float2 sA = *(const float2*)(s1p + i*8);
            float2 eA = *(const float2*)(e2p + i*8);
            float2 sB = *(const float2*)(s1p + i*8 + 8);
            float2 eB = *(const float2*)(e2p + i*8 + 8);
            float pA = penh[i], pB = penh[i+1];
            float x0 = sA.x + eA.x, x1 = sA.y + eA.y;
            float y0 = sB.x + eB.x, y1 = sB.y + eB.y;
            a0a = fmaxf(a0a, x0); a1a = fmaxf(a1a, x1);
            a0b = fmaxf(a0b, y0); a1b = fmaxf(a1b, y1);
            v0a = fmaxf(v0a, x0 + pA); v1a = fmaxf(v1a, x1 + pA);
            v0b = fmaxf(v0b, y0 + pB); v1b = fmaxf(v1b, y1 + pB);
        }
    }
    float mA0 = fmaxf(a0a, a0b), mA1 = fmaxf(a1a, a1b);
    float mV0 = fmaxf(v0a, v0b), mV1 = fmaxf(v1a, v1b);

    __syncthreads();   // A_s reads all done; safe to alias as Pp
    if (ih == 1) {
        float4* pp = (float4*)(Pp + r*4);
        *pp = make_float4(mA0, mA1, mV0, mV1);
    }
    __syncthreads();
    if (ih == 0) {
        float4 o = *(const float4*)(Pp + r*4);
        mA0 = fmaxf(mA0, o.x); mA1 = fmaxf(mA1, o.y);
        mV0 = fmaxf(mV0, o.z); mV1 = fmaxf(mV1, o.w);
        bool cond = jv || (mkf[kk] != 0.0f);
        int jg = j0 + jj, kg = k0 + kk;
        float2 e3v = *(const float2*)&g_e3n[((b*NN + jg)*NN + kg)*8 + cp];
        float base0 = t2s[jj*8 + cp]     + t3s[kk*8 + cp]     + tgs[cp]     + e3v.x;
        float base1 = t2s[jj*8 + cp + 1] + t3s[kk*8 + cp + 1] + tgs[cp + 1] + e3v.y;
        float p0 = cond ? (mA0 + base0) : fmaxf(mV0 + base0, NEGV);
        float p1 = cond ? (mA1 + base1) : fmaxf(mV1 + base1, NEGV);
        *(float2*)&Ps[(jj*8 + kk)*8 + cp] = make_float2(p0, p1);
    }
    __syncthreads();

    #pragma unroll
    for (int oi = 0; oi < 16; oi++) {
        int idx = t + 512*oi;
        int jk = idx >> 7, o = idx & 127;
        const float* pr = Ps + jk*8;
        float acc = 0.f;
        #pragma unroll
        for (int c = 0; c < 8; c++) acc += pr[c]*WU3s[c*128 + o];
        acc = fmaxf(acc, 0.0f);
        int jjx = jk >> 3, kkx = jk & 7;
        out_tri[(((long)b*NN + j0 + jjx)*NN + (k0 + kkx))*OD + o] = acc;
    }
}

// ---------------- fused pairwise MLP + masked max over i (f32x2 gemv) ----------------
__device__ __forceinline__ void ln_relu4(float* x, float4 s, float4 o) {
    float sum = x[0] + x[1] + x[2] + x[3];
    #pragma unroll
    for (int off = 16; off > 0; off >>= 1) sum += __shfl_xor_sync(0xffffffffu, sum, off);
    float mean = sum * 0.0078125f;
    float d0 = x[0]-mean, d1 = x[1]-mean, d2 = x[2]-mean, d3 = x[3]-mean;
    float q = d0*d0 + d1*d1 + d2*d2 + d3*d3;
    #pragma unroll
    for (int off = 16; off > 0; off >>= 1) q += __shfl_xor_sync(0xffffffffu, q, off);
    float rs = rsqrtf(q*0.0078125f + EPSV);
    x[0] = fmaxf(fmaf(s.x*rs, d0, o.x), 0.f);
    x[1] = fmaxf(fmaf(s.y*rs, d1, o.y), 0.f);
    x[2] = fmaxf(fmaf(s.z*rs, d2, o.z), 0.f);
    x[3] = fmaxf(fmaf(s.w*rs, d3, o.w), 0.f);
}

// GEMV over 6 staged rows using fma.rn.f32x2: 48 FFMA2 + 24 MOV per k4
// (vs 96 FFMA) — halves FMA-pipe ops; movs ride the idle ALU pipe.
__device__ __forceinline__ void gemv6(const float* eb, const float* W_s, int l,
                                      float a[6][4]) {
    unsigned long long acc[6][2];
    #pragma unroll
    for (int q = 0; q < 6; q++) {
        PK2(acc[q][0], a[q][0], a[q][1]);
        PK2(acc[q][1], a[q][2], a[q][3]);
    }
    const ulonglong2* W2 = (const ulonglong2*)W_s;
    #pragma unroll 2
    for (int k4 = 0; k4 < 32; k4++) {
        float4 v[6];
        #pragma unroll
        for (int q = 0; q < 6; q++) v[q] = ((const float4*)(eb + q*128))[k4];
        #pragma unroll
        for (int kk = 0; kk < 4; kk++) {
            ulonglong2 wp = W2[(k4*4 + kk)*32 + l];
            #pragma unroll
            for (int q = 0; q < 6; q++) {
                float f = (&v[q].x)[kk];
                unsigned long long ff; PK2DUP(ff, f);
                FMA2(acc[q][0], ff, wp.x, acc[q][0]);
                FMA2(acc[q][1], ff, wp.y, acc[q][1]);
            }
        }
    }
    #pragma unroll
    for (int q = 0; q < 6; q++) {
        UPK2(a[q][0], a[q][1], acc[q][0]);
        UPK2(a[q][2], a[q][3], acc[q][1]);
    }
}

#define PAIR_SMEM_FLOATS 56864
__global__ void __launch_bounds__(256,1) k_pair(
    const float* __restrict__ e,
    const float* __restrict__ Wme, const float* __restrict__ Wmlp1, const float* __restrict__ Wmlp2,
    const float* __restrict__ ln1s, const float* __restrict__ ln1o,
    const float* __restrict__ ln2s, const float* __restrict__ ln2o) {
    extern __shared__ float sm[];
    float* Wme_s = sm;
    float* W1_s  = sm + 16384;
    float* W2_s  = sm + 32768;
    float* ebuf  = sm + 49152;               // 8 warps * 6 rows * 128
    int*   lists = (int*)(sm + 55296);       // 8 cols * 64
    unsigned* smax = (unsigned*)(sm + 55808); // 8 cols * 128
    int*   offs  = (int*)(sm + 56832);       // 17

    int t = threadIdx.x, w = t >> 5, l = t & 31;
    int jt = blockIdx.x, half = blockIdx.y, b = blockIdx.z;

    {
        const float4* a  = (const float4*)Wme;
        const float4* c1 = (const float4*)Wmlp1;
        const float4* c2 = (const float4*)Wmlp2;
        float4* d0 = (float4*)Wme_s; float4* d1 = (float4*)W1_s; float4* d2 = (float4*)W2_s;
        for (int idx = t; idx < 4096; idx += 256) { d0[idx] = a[idx]; d1[idx] = c1[idx]; d2[idx] = c2[idx]; }
    }
    unsigned negkey = fkey(NEGV);
    for (int idx = t; idx < 1024; idx += 256) smax[idx] = negkey;

    int jw = jt*8 + w;
    int* list = lists + w*64;
    int cnt = 0;
    for (int base = 0; base < 64; base += 32) {
        int i = half*64 + base + l;
        int f = g_adj[(b*NN + i)*NN + jw] ? 1 : 0;
        unsigned bal = __ballot_sync(0xffffffffu, f);
        int pos = cnt + __popc(bal & ((1u << l) - 1u));
        if (f) list[pos] = i;
        cnt += __popc(bal);
    }
    if (l == 0) offs[9 + w] = cnt;
    __syncthreads();
    if (t == 0) {
        int s = 0;
        #pragma unroll
        for (int q = 0; q < 8; q++) { offs[q] = s; s += offs[9 + q]; }
        offs[8] = s;
    }
    __syncthreads();
    int E = offs[8];

    int c0 = 4*l;
    float4 mgg = *(const float4*)&g_msgg[b*OD + c0];
    float4 p1s = *(const float4*)&ln1s[c0];
    float4 p1o = *(const float4*)&ln1o[c0];
    float4 p2s = *(const float4*)&ln2s[c0];
    float4 p2o = *(const float4*)&ln2o[c0];

    float* eb = ebuf + w*768;

    for (int g0 = w*6; g0 < E; g0 += 48) {
        int nv = E - g0; if (nv > 6) nv = 6;
        int id[6], jl[6];
        #pragma unroll
        for (int q = 0; q < 6; q++) {
            int fi = g0 + (q < nv ? q : nv-1);
            int c = 0;
            #pragma unroll
            for (int x = 1; x < 8; x++) if (fi >= offs[x]) c = x;
            jl[q] = c;
            id[q] = lists[c*64 + fi - offs[c]];
        }
        float a[6][4];
        #pragma unroll
        for (int q = 0; q < 6; q++) {
            int jq = jt*8 + jl[q];
            float4 m1 = *(const float4*)&g_msg1[(b*NN + jq)*OD + c0];
            float4 m2 = *(const float4*)&g_msg2[(b*NN + id[q])*OD + c0];
            a[q][0] = m1.x + m2.x + mgg.x; a[q][1] = m1.y + m2.y + mgg.y;
            a[q][2] = m1.z + m2.z + mgg.z; a[q][3] = m1.w + m2.w + mgg.w;
        }
        __syncwarp();
        #pragma unroll
        for (int q = 0; q < 6; q++) {
            int jq = jt*8 + jl[q];
            ((float4*)(eb + q*128))[l] = *(const float4*)&e[(((long)b*NN + id[q])*NN + jq)*128 + c0];
        }
        __syncwarp();

        gemv6(eb, Wme_s, l, a);
        #pragma unroll
        for (int q = 0; q < 6; q++) ln_relu4(a[q], p1s, p1o);
        __syncwarp();
        #pragma unroll
        for (int q = 0; q < 6; q++)
            ((float4*)(eb + q*128))[l] = make_float4(a[q][0], a[q][1], a[q][2], a[q][3]);
        __syncwarp();

        float a2[6][4];
        #pragma unroll
        for (int q = 0; q < 6; q++) { a2[q][0]=0; a2[q][1]=0; a2[q][2]=0; a2[q][3]=0; }
        gemv6(eb, W1_s, l, a2);
        #pragma unroll
        for (int q = 0; q < 6; q++) ln_relu4(a2[q], p2s, p2o);
        __syncwarp();
        #pragma unroll
        for (int q = 0; q < 6; q++)
            ((float4*)(eb + q*128))[l] = make_float4(a2[q][0], a2[q][1], a2[q][2], a2[q][3]);
        __syncwarp();

        float a3[6][4];
        #pragma unroll
        for (int q = 0; q < 6; q++) { a3[q][0]=0; a3[q][1]=0; a3[q][2]=0; a3[q][3]=0; }
        gemv6(eb, W2_s, l, a3);
        #pragma unroll
        for (int q = 0; q < 6; q++) {
            if (q < nv) {
                unsigned* sj = smax + jl[q]*128 + c0;
                atomicMax(&sj[0], fkey(a3[q][0]));
                atomicMax(&sj[1], fkey(a3[q][1]));
                atomicMax(&sj[2], fkey(a3[q][2]));
                atomicMax(&sj[3], fkey(a3[q][3]));
            }
        }
    }
    __syncthreads();
    for (int idx = t; idx < 1024; idx += 256) {
        int jl2 = idx >> 7, c = idx & 127;
        g_pmax[((b*2 + half)*NN + jt*8 + jl2)*OD + c] = fdec(smax[idx]);
    }
}

// ---------------- final: msgs out + ret = LN(zU1 + msgs@WU2) ----------------
__global__ void __launch_bounds__(128) k_final(const float* __restrict__ WU2,
                                               const float* __restrict__ lnfs,
                                               const float* __restrict__ lnfo,
                                               float* __restrict__ out_ret,
                                               float* __restrict__ out_msgs) {
    int bn = blockIdx.x;
    int b = bn >> 7;
    int c = threadIdx.x, l = c & 31, w = c >> 5;
    int n = bn & 127;
    __shared__ float ms[128];
    __shared__ float red[4];
    float m = fmaxf(g_pmax[((b*2 + 0)*NN + n)*OD + c],
                    g_pmax[((b*2 + 1)*NN + n)*OD + c]);
    out_msgs[bn*OD + c] = m;
    ms[c] = m;
    __syncthreads();
    float acc = g_zU1[bn*OD + c];
    #pragma unroll 4
    for (int k = 0; k < 128; k++) acc += ms[k]*WU2[k*OD + c];
    float s = acc;
    #pragma unroll
    for (int off = 16; off > 0; off >>= 1) s += __shfl_xor_sync(0xffffffffu, s, off);
    if (l == 0) red[w] = s;
    __syncthreads();
    float mean = (red[0] + red[1] + red[2] + red[3]) * 0.0078125f;
    float d = acc - mean;
    float q = d*d;
    #pragma unroll
    for (int off = 16; off > 0; off >>= 1) q += __shfl_xor_sync(0xffffffffu, q, off);
    __syncthreads();
    if (l == 0) red[w] = q;
    __syncthreads();
    float var = (red[0] + red[1] + red[2] + red[3]) * 0.0078125f;
    out_ret[bn*OD + c] = fmaf(lnfs[c]*rsqrtf(var + EPSV), d, lnfo[c]);
}

extern "C" void kernel_launch(void* const* d_in, const int* in_sizes, int n_in,
                              void* d_out, int out_size) {
    const float* z    = (const float*)d_in[0];
    const float* e    = (const float*)d_in[1];
    const float* gf   = (const float*)d_in[2];
    const void*  maskp= d_in[3];
    const void*  adjp = d_in[4];
    const float* Wt1  = (const float*)d_in[5];
    const float* Wt2  = (const float*)d_in[6];
    const float* Wt3  = (const float*)d_in[7];
    const float* We1  = (const float*)d_in[8];
    const float* We2  = (const float*)d_in[9];
    const float* We3  = (const float*)d_in[10];
    const float* Wg   = (const float*)d_in[11];
    const float* Wm1  = (const float*)d_in[12];
    const float* Wm2  = (const float*)d_in[13];
    const float* Wme  = (const float*)d_in[14];
    const float* Wmg  = (const float*)d_in[15];
    const float* ln1s = (const float*)d_in[16];
    const float* ln1o = (const float*)d_in[17];
    const float* Wmlp1= (const float*)d_in[18];
    const float* ln2s = (const float*)d_in[19];
    const float* ln2o = (const float*)d_in[20];
    const float* Wmlp2= (const float*)d_in[21];
    const float* WU1  = (const float*)d_in[22];
    const float* WU2  = (const float*)d_in[23];
    const float* WU3  = (const float*)d_in[24];
    const float* lnfs = (const float*)d_in[25];
    const float* lnfo = (const float*)d_in[26];

    float* out      = (float*)d_out;
    float* out_ret  = out;                 // (B,N,OUT)
    float* out_msgs = out + BB*NN*OD;      // (B,N,OUT)
    float* out_tri  = out + 2*BB*NN*OD;    // (B,N,N,OUT)

    cudaFuncSetAttribute(k_node, cudaFuncAttributeMaxDynamicSharedMemorySize,
                         NODE_SMEM_FLOATS*4);
    cudaFuncSetAttribute(k_trimax, cudaFuncAttributeMaxDynamicSharedMemorySize,
                         TRI_SMEM_FLOATS*4);
    cudaFuncSetAttribute(k_pair, cudaFuncAttributeMaxDynamicSharedMemorySize,
                         PAIR_SMEM_FLOATS*4);

    // slot 4 (the profiled one) = k_pair, verifying the f32x2 gemv.
    k_convbool<<<64, 256>>>(maskp, adjp);
    k_graph<<<BB, 128>>>(gf, Wg, Wmg);
    k_node<<<BB*NN/4, 512, NODE_SMEM_FLOATS*4>>>(z, Wm1, Wm2, WU1, Wt1, Wt2, Wt3);
    k_pair<<<dim3(16,2,BB), 256, PAIR_SMEM_FLOATS*4>>>(e, Wme, Wmlp1, Wmlp2,
                                                       ln1s, ln1o, ln2s, ln2o);
    k_eproj<<<BB*NN*NN/64, 256>>>(e, We1, We2, We3);
    k_trimax<<<dim3(16,16,BB), 512, TRI_SMEM_FLOATS*4>>>(WU3, out_tri);
    k_final<<<BB*NN, 128>>>(WU2, lnfs, lnfo, out_ret, out_msgs);
}